// round 6
// baseline (speedup 1.0000x reference)
#include <cuda_runtime.h>
#include <cuda_fp16.h>
#include <cstdint>

#define NB 2
#define NN 512
#define NE 128
#define NH 256
#define NTHR 512

// A tile: 128 rows x 296 halves (592 B stride, 37 segs -> conflict-free)
#define STRA_B 592
// B chunk: 256 n-rows x 32 k halves, padded to 80 B rows (5 segs -> conflict-free)
#define STRB_B 80
#define BCHUNK_B 20480
#define OFF_A   0
#define OFF_B   75776
#define OFF_P   116736
#define OFF_W3  117760
#define OFF_NI  118784
#define OFF_RED 119296
#define SMEM_REQ 121856

// device scratch (allocation-free rule)
__device__ float g_P[NB * NN * NH];      // hi @ W1[0:128]   exact fp32
__device__ float g_Q[NB * NN * NH];      // hj @ W1[128:256] exact fp32
__device__ float g_raw[NB * NN * NN];
__device__ __half g_B1h[5 * 256 * 32];   // L1 B: [chunk][n][k] fp16
__device__ __half g_B2h[9 * 256 * 32];   // L2 B: [chunk][n][k] fp16

// ---------------- PTX helpers ----------------
__device__ __forceinline__ uint32_t smem_u32(const void* p) {
    uint32_t a;
    asm("{ .reg .u64 t; cvta.to.shared.u64 t, %1; cvt.u32.u64 %0, t; }" : "=r"(a) : "l"(p));
    return a;
}
#define LDSM4(R, A) \
    asm volatile("ldmatrix.sync.aligned.m8n8.x4.shared.b16 {%0,%1,%2,%3}, [%4];" \
        : "=r"((R)[0]), "=r"((R)[1]), "=r"((R)[2]), "=r"((R)[3]) : "r"(A))
#define LDSM2(R, A) \
    asm volatile("ldmatrix.sync.aligned.m8n8.x2.shared.b16 {%0,%1}, [%2];" \
        : "=r"((R)[0]), "=r"((R)[1]) : "r"(A))
#define MMA_F16(C, Ar, Br) \
    asm volatile("mma.sync.aligned.m16n8k16.row.col.f32.f16.f16.f32 " \
        "{%0,%1,%2,%3}, {%4,%5,%6,%7}, {%8,%9}, {%0,%1,%2,%3};" \
        : "+f"((C)[0]), "+f"((C)[1]), "+f"((C)[2]), "+f"((C)[3]) \
        : "r"((Ar)[0]), "r"((Ar)[1]), "r"((Ar)[2]), "r"((Ar)[3]), \
          "r"((Br)[0]), "r"((Br)[1]))
#define CP16(d, s)  asm volatile("cp.async.ca.shared.global [%0], [%1], 16;" :: "r"(d), "l"(s))
#define CPCOMMIT()  asm volatile("cp.async.commit_group;" ::: "memory")
#define CPWAIT1()   asm volatile("cp.async.wait_group 1;" ::: "memory")

// ---------------- prep kernels ----------------
__global__ void precompute_PQ(const float* __restrict__ node, const float* __restrict__ W1) {
    const int row = blockIdx.x;
    const int t = threadIdx.x;
    __shared__ float ns[NE];
    if (t < NE) ns[t] = node[row * NE + t];
    __syncthreads();
    float p = 0.f, q = 0.f;
#pragma unroll 8
    for (int e = 0; e < NE; e++) {
        float nv = ns[e];
        p = fmaf(nv, W1[e * NH + t], p);
        q = fmaf(nv, W1[(NE + e) * NH + t], q);
    }
    g_P[row * NH + t] = p;
    g_Q[row * NH + t] = q;
}

__global__ void prep_Bh(const float* __restrict__ W1, const float* __restrict__ b1,
                        const float* __restrict__ W2, const float* __restrict__ b2) {
    int idx = blockIdx.x * 256 + threadIdx.x;    // 0 .. 14*8192-1
    bool isB1 = idx < 5 * 8192;
    int local = isB1 ? idx : idx - 5 * 8192;
    int c = local >> 13, n = (local >> 5) & 255, kk = local & 31;
    int k = c * 32 + kk;
    if (isB1) {
        float v = (k < 128) ? W1[(256 + k) * NH + n]
                : (k == 128) ? W1[384 * NH + n]     // euclid coeff (A col = d)
                : (k == 129) ? b1[n] : 0.f;          // bias (A col = 1)
        g_B1h[local] = __float2half_rn(v);
    } else {
        float v = (k < 256) ? W2[k * NH + n]
                : (k == 256) ? b2[n] : 0.f;          // b2 (A col = 1)
        g_B2h[local] = __float2half_rn(v);
    }
}

// ---------------- GEMM inner: one 32-k chunk = 2 k16 steps (warp tile 32x64) ----
__device__ __forceinline__ void mma_chunk2(float (&acc)[2][8][4],
                                           uint32_t aK, uint32_t bB) {
#pragma unroll
    for (int ks = 0; ks < 2; ks++) {
        uint32_t a[2][4], bf[8][2];
        uint32_t aa = aK + ks * 32;       // +16 halves
        uint32_t ba = bB + ks * 32;
#pragma unroll
        for (int mt = 0; mt < 2; mt++) LDSM4(a[mt], aa + mt * 16 * STRA_B);
#pragma unroll
        for (int nt = 0; nt < 8; nt++) LDSM2(bf[nt], ba + nt * 8 * STRB_B);
#pragma unroll
        for (int mt = 0; mt < 2; mt++)
#pragma unroll
            for (int nt = 0; nt < 8; nt++) MMA_F16(acc[mt][nt], a[mt], bf[nt]);
    }
}

// ---------------- main fused kernel ----------------
__global__ void __launch_bounds__(NTHR, 1)
edge_mlp_mma(const float* __restrict__ node, const float* __restrict__ euclid,
             const float* __restrict__ W3, const float* __restrict__ b3) {
    extern __shared__ char smc[];
    __half* smA  = (__half*)(smc + OFF_A);
    float* P_s   = (float*)(smc + OFF_P);
    float* w3_s  = (float*)(smc + OFF_W3);
    float* ni_s  = (float*)(smc + OFF_NI);
    float* red_s = (float*)(smc + OFF_RED);
    const uint32_t sb = smem_u32(smc);

    const int tid = threadIdx.x, L = tid & 31, wid = tid >> 5;
    const int mw = wid >> 2, nw = wid & 3;           // 4 x 4 warp grid
    const int m0 = mw * 32, n0 = nw * 64;
    const int b = blockIdx.z, i = blockIdx.y, j0 = blockIdx.x << 7;

    // prefetch L1 chunk 0 -> buf0 (overlaps A staging): 1024 16B segs / 512 thr
    {
        const __half* src = g_B1h;
#pragma unroll
        for (int r = 0; r < 2; r++) {
            int seg = tid + r * NTHR, n = seg >> 2, s = seg & 3;
            CP16(sb + OFF_B + n * STRB_B + s * 16, src + n * 32 + s * 8);
        }
        CPCOMMIT();
    }

    // stage small vectors
    if (tid < 256) {
        P_s[tid]  = g_P[(b * NN + i) * NH + tid];
        w3_s[tid] = W3[tid];
    }
    if (tid >= 256 && tid < 256 + NE)
        ni_s[tid - 256] = node[(size_t)(b * NN + i) * NE + (tid - 256)];
    __syncthreads();

    // ---- stage A (L1): rows = 128 j-pairs, cols [habs(128) | d | 1 | 0..(k160)]
    {
        int row = tid >> 2, q4 = tid & 3;            // 4 threads per row, 32 cols each
        const float4* nj = (const float4*)(node + (size_t)(b * NN + j0 + row) * NE);
        __half* dst = (__half*)((char*)smA + row * STRA_B) + q4 * 32;
        const float* nip = ni_s + q4 * 32;
#pragma unroll
        for (int q = 0; q < 8; q++) {
            float4 v = nj[q4 * 8 + q];
            __half2 h0 = __floats2half2_rn(fabsf(nip[q * 4 + 0] - v.x),
                                           fabsf(nip[q * 4 + 1] - v.y));
            __half2 h1v = __floats2half2_rn(fabsf(nip[q * 4 + 2] - v.z),
                                            fabsf(nip[q * 4 + 3] - v.w));
            *(__half2*)(dst + q * 4)     = h0;
            *(__half2*)(dst + q * 4 + 2) = h1v;
        }
        if (tid < 128) {
            float d = euclid[(size_t)(b * NN + i) * NN + j0 + tid];
            __half* rr = (__half*)((char*)smA + tid * STRA_B);
            rr[128] = __float2half_rn(d);
            rr[129] = __float2half_rn(1.0f);
#pragma unroll
            for (int u = 65; u < 80; u++) ((uint32_t*)rr)[u] = 0u;  // halves 130..159
        }
    }

    float acc[2][8][4];
#pragma unroll
    for (int mt = 0; mt < 2; mt++)
#pragma unroll
        for (int nt = 0; nt < 8; nt++)
#pragma unroll
            for (int r = 0; r < 4; r++) acc[mt][nt][r] = 0.f;

    // per-thread ldmatrix bases
    const uint32_t rowA = (L & 7) + ((L >> 3) & 1) * 8;
    const uint32_t colA = (L >> 4) * 16;
    const uint32_t aBase = sb + OFF_A + (m0 + rowA) * STRA_B + colA;
    const uint32_t bOff = (n0 + (L & 7)) * STRB_B + ((L >> 3) & 1) * 16;

    // ---- one GEMM layer over 32-k chunks, double-buffered B via cp.async ----
    auto run_layer = [&](const __half* gB, int nch, const __half* nextB, int phase) {
        for (int c = 0; c < nch; c++) {
            const __half* pre = (c + 1 < nch) ? (gB + (c + 1) * 8192) : nextB;
            if (pre) {
                uint32_t dst = sb + OFF_B + (((c + 1 + phase) & 1) ? BCHUNK_B : 0);
#pragma unroll
                for (int r = 0; r < 2; r++) {
                    int seg = tid + r * NTHR, n = seg >> 2, s = seg & 3;
                    CP16(dst + n * STRB_B + s * 16, pre + n * 32 + s * 8);
                }
            }
            CPCOMMIT();
            CPWAIT1();
            __syncthreads();
            uint32_t bBase = sb + OFF_B + (((c + phase) & 1) ? BCHUNK_B : 0) + bOff;
            mma_chunk2(acc, aBase + c * 64, bBase);
            __syncthreads();   // WAR fence before this buffer is rewritten
        }
    };

    run_layer(g_B1h, 5, g_B2h, 0);   // last iter prefetches L2 chunk0 -> buf1

    // ---- epilogue 1: h1 = relu(acc + P[i] + Q[j]) -> fp16 A tile in place ----
#pragma unroll
    for (int mt = 0; mt < 2; mt++) {
        int r0 = m0 + mt * 16 + (L >> 2);
        const float* qA = g_Q + ((size_t)(b * NN + j0 + r0)) * NH;
        const float* qB = qA + 8 * NH;
#pragma unroll
        for (int nt = 0; nt < 8; nt++) {
            int cb = n0 + nt * 8 + (L & 3) * 2;
            float p0 = P_s[cb], p1 = P_s[cb + 1];
            float2 qa = *(const float2*)(qA + cb);
            float2 qb = *(const float2*)(qB + cb);
            __half2 v0 = __floats2half2_rn(fmaxf(acc[mt][nt][0] + p0 + qa.x, 0.f),
                                           fmaxf(acc[mt][nt][1] + p1 + qa.y, 0.f));
            __half2 v1 = __floats2half2_rn(fmaxf(acc[mt][nt][2] + p0 + qb.x, 0.f),
                                           fmaxf(acc[mt][nt][3] + p1 + qb.y, 0.f));
            *(__half2*)((char*)smA + r0 * STRA_B + cb * 2) = v0;
            *(__half2*)((char*)smA + (r0 + 8) * STRA_B + cb * 2) = v1;
            acc[mt][nt][0] = 0.f; acc[mt][nt][1] = 0.f;
            acc[mt][nt][2] = 0.f; acc[mt][nt][3] = 0.f;
        }
    }
    if (tid < 128) {
        __half* rr = (__half*)((char*)smA + tid * STRA_B);
        rr[256] = __float2half_rn(1.0f);   // bias column for L2
        rr[257] = __float2half_rn(0.0f);
#pragma unroll
        for (int u = 129; u < 144; u++) ((uint32_t*)rr)[u] = 0u;  // halves 258..287
    }
    __syncthreads();

    run_layer(g_B2h, 9, nullptr, 5);

    // ---- epilogue 2: out = relu(acc) . W3  (b2 folded via 1-column) ----
    float w3c[16];
#pragma unroll
    for (int nt = 0; nt < 8; nt++) {
        int cb = n0 + nt * 8 + (L & 3) * 2;
        w3c[nt * 2] = w3_s[cb];
        w3c[nt * 2 + 1] = w3_s[cb + 1];
    }
    float rs[4];
#pragma unroll
    for (int mt = 0; mt < 2; mt++) {
        float s0 = 0.f, s1 = 0.f;
#pragma unroll
        for (int nt = 0; nt < 8; nt++) {
            s0 = fmaf(fmaxf(acc[mt][nt][0], 0.f), w3c[nt * 2], s0);
            s0 = fmaf(fmaxf(acc[mt][nt][1], 0.f), w3c[nt * 2 + 1], s0);
            s1 = fmaf(fmaxf(acc[mt][nt][2], 0.f), w3c[nt * 2], s1);
            s1 = fmaf(fmaxf(acc[mt][nt][3], 0.f), w3c[nt * 2 + 1], s1);
        }
        rs[mt * 2] = s0;
        rs[mt * 2 + 1] = s1;
    }
#pragma unroll
    for (int r = 0; r < 4; r++) {
        float v = rs[r];
        v += __shfl_xor_sync(0xffffffffu, v, 1);
        v += __shfl_xor_sync(0xffffffffu, v, 2);
        if ((L & 3) == 0) {
            int m = m0 + (r >> 1) * 16 + (r & 1) * 8 + (L >> 2);
            red_s[m * 4 + nw] = v;
        }
    }
    __syncthreads();
    if (tid < 128) {
        float o = red_s[tid * 4] + red_s[tid * 4 + 1] +
                  red_s[tid * 4 + 2] + red_s[tid * 4 + 3] + b3[0];
        g_raw[(size_t)(b * NN + i) * NN + j0 + tid] = o;
    }
}

// ---------------- symmetrize + zero diagonal ----------------
__global__ void symmetrize(float* __restrict__ out) {
    int idx = blockIdx.x * 256 + threadIdx.x;
    int b = idx >> 18;
    int r = idx & 262143;
    int i = r >> 9;
    int j = r & 511;
    float v = 0.f;
    if (i != j)
        v = 0.5f * (g_raw[idx] + g_raw[(b << 18) + (j << 9) + i]);
    out[idx] = v;
}

extern "C" void kernel_launch(void* const* d_in, const int* in_sizes, int n_in,
                              void* d_out, int out_size) {
    const float* node   = (const float*)d_in[0];
    const float* euclid = (const float*)d_in[2];
    const float* W1 = (const float*)d_in[3];
    const float* b1 = (const float*)d_in[4];
    const float* W2 = (const float*)d_in[5];
    const float* b2 = (const float*)d_in[6];
    const float* W3 = (const float*)d_in[7];
    const float* b3 = (const float*)d_in[8];
    float* out = (float*)d_out;

    cudaFuncSetAttribute(edge_mlp_mma, cudaFuncAttributeMaxDynamicSharedMemorySize,
                         SMEM_REQ);

    precompute_PQ<<<NB * NN, 256>>>(node, W1);
    prep_Bh<<<448, 256>>>(W1, b1, W2, b2);
    dim3 grid(NN / 128, NN, NB);
    edge_mlp_mma<<<grid, NTHR, SMEM_REQ>>>(node, euclid, W3, b3);
    symmetrize<<<(NB * NN * NN) / 256, 256>>>(out);
}